// round 1
// baseline (speedup 1.0000x reference)
#include <cuda_runtime.h>
#include <math.h>
#include <float.h>

#define DIM     1024
#define HEADS   16
#define DHEAD   64
#define INNER   1024
#define SEQ     2048
#define BATCH   2
#define ROWS    (BATCH * SEQ)        // 4096
#define ATTN_SCALE 0.125f            // 64^-0.5
#define LN_EPS  1e-5f

// ---------------- scratch (__device__ globals: no runtime allocation) -------
__device__ float g_xn[(size_t)ROWS * DIM];                 // 16 MB
__device__ float g_q [(size_t)BATCH * HEADS * SEQ * DHEAD]; // 16 MB
__device__ float g_k [(size_t)BATCH * HEADS * SEQ * DHEAD];
__device__ float g_v [(size_t)BATCH * HEADS * SEQ * DHEAD];
__device__ float g_ao[(size_t)ROWS * INNER];               // 16 MB

// ---------------- LayerNorm: one block (256 thr) per row ---------------------
__global__ __launch_bounds__(256) void ln_kernel(
    const float* __restrict__ x,
    const float* __restrict__ gamma,
    const float* __restrict__ beta)
{
    int row = blockIdx.x;
    int t   = threadIdx.x;                     // 256 threads, 4 floats each
    const float4* xr = (const float4*)(x + (size_t)row * DIM);
    float4 v = xr[t];

    __shared__ float red[32];
    // mean
    float s = v.x + v.y + v.z + v.w;
    #pragma unroll
    for (int o = 16; o > 0; o >>= 1) s += __shfl_xor_sync(0xffffffffu, s, o);
    if ((t & 31) == 0) red[t >> 5] = s;
    __syncthreads();
    if (t < 32) {
        float z = (t < 8) ? red[t] : 0.f;
        #pragma unroll
        for (int o = 4; o > 0; o >>= 1) z += __shfl_xor_sync(0xffffffffu, z, o);
        if (t == 0) red[0] = z * (1.0f / DIM);
    }
    __syncthreads();
    float mu = red[0];
    __syncthreads();

    float4 d4 = make_float4(v.x - mu, v.y - mu, v.z - mu, v.w - mu);
    float s2 = d4.x*d4.x + d4.y*d4.y + d4.z*d4.z + d4.w*d4.w;
    #pragma unroll
    for (int o = 16; o > 0; o >>= 1) s2 += __shfl_xor_sync(0xffffffffu, s2, o);
    if ((t & 31) == 0) red[t >> 5] = s2;
    __syncthreads();
    if (t < 32) {
        float z = (t < 8) ? red[t] : 0.f;
        #pragma unroll
        for (int o = 4; o > 0; o >>= 1) z += __shfl_xor_sync(0xffffffffu, z, o);
        if (t == 0) red[0] = z * (1.0f / DIM);
    }
    __syncthreads();
    float rinv = rsqrtf(red[0] + LN_EPS);

    float4 g = ((const float4*)gamma)[t];
    float4 bt = ((const float4*)beta)[t];
    float4 o4;
    o4.x = d4.x * rinv * g.x + bt.x;
    o4.y = d4.y * rinv * g.y + bt.y;
    o4.z = d4.z * rinv * g.z + bt.z;
    o4.w = d4.w * rinv * g.w + bt.w;
    ((float4*)(g_xn + (size_t)row * DIM))[t] = o4;
}

// ---------------- 128x128x16 fp32 GEMM, 256 threads, 8x8 microtile -----------
// MODE 0: C = g_xn @ w_qkv, scatter epilogue into g_q/g_k/g_v (head-major)
// MODE 1: C = g_ao @ w_out -> out
template<int NCOLS, int MODE>
__global__ __launch_bounds__(256) void gemm128(
    const float* __restrict__ A,
    const float* __restrict__ Bw,
    float* __restrict__ C)
{
    __shared__ float As[16][128];
    __shared__ float Bs[16][128];

    int tid = threadIdx.x;
    int m0 = blockIdx.y * 128;
    int n0 = blockIdx.x * 128;
    int ty = tid >> 4, tx = tid & 15;

    float acc[8][8];
    #pragma unroll
    for (int i = 0; i < 8; i++)
        #pragma unroll
        for (int j = 0; j < 8; j++) acc[i][j] = 0.f;

    for (int k0 = 0; k0 < 1024; k0 += 16) {
        #pragma unroll
        for (int t2 = 0; t2 < 2; t2++) {
            int vv = tid + t2 * 256;            // 0..511
            int r  = vv >> 2;                   // 0..127
            int c4 = vv & 3;                    // 0..3
            float4 av = *(const float4*)(A + (size_t)(m0 + r) * 1024 + k0 + c4 * 4);
            As[c4*4+0][r] = av.x; As[c4*4+1][r] = av.y;
            As[c4*4+2][r] = av.z; As[c4*4+3][r] = av.w;
        }
        #pragma unroll
        for (int t2 = 0; t2 < 2; t2++) {
            int vv = tid + t2 * 256;
            int r  = vv >> 5;                   // 0..15
            int c4 = vv & 31;                   // 0..31
            *(float4*)&Bs[r][c4*4] =
                *(const float4*)(Bw + (size_t)(k0 + r) * NCOLS + n0 + c4 * 4);
        }
        __syncthreads();

        #pragma unroll
        for (int k = 0; k < 16; k++) {
            float a[8], b[8];
            *(float4*)(a)     = *(float4*)&As[k][ty*8];
            *(float4*)(a + 4) = *(float4*)&As[k][ty*8 + 4];
            *(float4*)(b)     = *(float4*)&Bs[k][tx*8];
            *(float4*)(b + 4) = *(float4*)&Bs[k][tx*8 + 4];
            #pragma unroll
            for (int i = 0; i < 8; i++)
                #pragma unroll
                for (int j = 0; j < 8; j++)
                    acc[i][j] = fmaf(a[i], b[j], acc[i][j]);
        }
        __syncthreads();
    }

    #pragma unroll
    for (int i = 0; i < 8; i++) {
        int r = m0 + ty * 8 + i;
        #pragma unroll
        for (int j = 0; j < 8; j++) {
            int c = n0 + tx * 8 + j;
            if (MODE == 0) {
                int which = c >> 10;            // 0=q 1=k 2=v
                int cc = c & 1023;
                int h  = cc >> 6;
                int dd = cc & 63;
                int b_ = r >> 11;               // batch
                int n  = r & 2047;
                float* dst = (which == 0) ? g_q : (which == 1) ? g_k : g_v;
                dst[(((size_t)b_ * HEADS + h) * SEQ + n) * DHEAD + dd] = acc[i][j];
            } else {
                C[(size_t)r * NCOLS + c] = acc[i][j];
            }
        }
    }
}

// ---------------- flash attention: 64-row Q tile per block -------------------
// grid: (SEQ/64 = 32, BATCH*HEADS = 32), 256 threads, dynamic smem ~70 KB
#define QTP 68   // padded row stride (floats), 16B-aligned
__global__ __launch_bounds__(256) void attn_kernel()
{
    int qt = blockIdx.x;                 // query tile
    int bh = blockIdx.y;                 // fused batch*head
    const float* Qg = g_q + (size_t)bh * SEQ * DHEAD + (size_t)qt * 64 * DHEAD;
    const float* Kg = g_k + (size_t)bh * SEQ * DHEAD;
    const float* Vg = g_v + (size_t)bh * SEQ * DHEAD;

    extern __shared__ float sm[];
    float* Qs  = sm;                 // 64 x QTP
    float* Ks  = Qs + 64 * QTP;
    float* Vs  = Ks + 64 * QTP;
    float* Ss  = Vs + 64 * QTP;
    float* msm = Ss + 64 * QTP;      // 64
    float* lsm = msm + 64;
    float* alp = lsm + 64;

    int tid = threadIdx.x;
    int ty = tid >> 4, tx = tid & 15;

    for (int i = tid; i < 64 * 64; i += 256) {
        int r = i >> 6, c = i & 63;
        Qs[r * QTP + c] = Qg[r * DHEAD + c];
    }
    if (tid < 64) { msm[tid] = -INFINITY; lsm[tid] = 0.f; }

    float o[4][4];
    #pragma unroll
    for (int i = 0; i < 4; i++)
        #pragma unroll
        for (int j = 0; j < 4; j++) o[i][j] = 0.f;

    __syncthreads();

    for (int kt = 0; kt < SEQ / 64; kt++) {
        for (int i = tid; i < 64 * 64; i += 256) {
            int r = i >> 6, c = i & 63;
            Ks[r * QTP + c] = Kg[(size_t)(kt * 64 + r) * DHEAD + c];
            Vs[r * QTP + c] = Vg[(size_t)(kt * 64 + r) * DHEAD + c];
        }
        __syncthreads();

        // S = Q K^T (64x64x64)
        float s[4][4];
        #pragma unroll
        for (int i = 0; i < 4; i++)
            #pragma unroll
            for (int j = 0; j < 4; j++) s[i][j] = 0.f;

        #pragma unroll 16
        for (int d = 0; d < 64; d++) {
            float a[4], b[4];
            #pragma unroll
            for (int i = 0; i < 4; i++) a[i] = Qs[(ty*4 + i) * QTP + d];
            #pragma unroll
            for (int j = 0; j < 4; j++) b[j] = Ks[(tx*4 + j) * QTP + d];
            #pragma unroll
            for (int i = 0; i < 4; i++)
                #pragma unroll
                for (int j = 0; j < 4; j++)
                    s[i][j] = fmaf(a[i], b[j], s[i][j]);
        }

        #pragma unroll
        for (int i = 0; i < 4; i++) {
            int gi = qt * 64 + ty * 4 + i;
            #pragma unroll
            for (int j = 0; j < 4; j++) {
                int gj = kt * 64 + tx * 4 + j;
                float val = s[i][j] * ATTN_SCALE;
                if (gi == gj) val = -3.0e38f;   // diagonal masked out
                Ss[(ty*4 + i) * QTP + tx*4 + j] = val;
            }
        }
        __syncthreads();

        // online softmax bookkeeping: one thread per row
        if (tid < 64) {
            int r = tid;
            float m_old = msm[r];
            float mn = m_old;
            #pragma unroll 8
            for (int j = 0; j < 64; j++) mn = fmaxf(mn, Ss[r * QTP + j]);
            float al = __expf(m_old - mn);
            float l = lsm[r] * al;
            #pragma unroll 8
            for (int j = 0; j < 64; j++) {
                float p = __expf(Ss[r * QTP + j] - mn);
                l += p;
                Ss[r * QTP + j] = p;
            }
            msm[r] = mn; lsm[r] = l; alp[r] = al;
        }
        __syncthreads();

        // O = O*alpha + P @ V
        float al[4];
        #pragma unroll
        for (int i = 0; i < 4; i++) al[i] = alp[ty*4 + i];
        #pragma unroll
        for (int i = 0; i < 4; i++)
            #pragma unroll
            for (int j = 0; j < 4; j++) o[i][j] *= al[i];

        #pragma unroll 16
        for (int j = 0; j < 64; j++) {
            float p[4], vv[4];
            #pragma unroll
            for (int i = 0; i < 4; i++) p[i] = Ss[(ty*4 + i) * QTP + j];
            #pragma unroll
            for (int c = 0; c < 4; c++) vv[c] = Vs[j * QTP + tx*4 + c];
            #pragma unroll
            for (int i = 0; i < 4; i++)
                #pragma unroll
                for (int c = 0; c < 4; c++)
                    o[i][c] = fmaf(p[i], vv[c], o[i][c]);
        }
        __syncthreads();
    }

    // epilogue: write to g_ao in [b, n, h*64+d] layout for the out-projection
    int b_ = bh / HEADS;
    int h  = bh % HEADS;
    #pragma unroll
    for (int i = 0; i < 4; i++) {
        int rloc = ty * 4 + i;
        int n = qt * 64 + rloc;
        float linv = 1.0f / lsm[rloc];
        #pragma unroll
        for (int j = 0; j < 4; j++) {
            int c = tx * 4 + j;
            g_ao[((size_t)b_ * SEQ + n) * INNER + h * DHEAD + c] = o[i][j] * linv;
        }
    }
}

#define ATTN_SMEM ((4 * 64 * QTP + 3 * 64) * (int)sizeof(float))

// ---------------- launcher ---------------------------------------------------
extern "C" void kernel_launch(void* const* d_in, const int* in_sizes, int n_in,
                              void* d_out, int out_size)
{
    const float* x     = (const float*)d_in[0];
    const float* gamma = (const float*)d_in[1];
    const float* beta  = (const float*)d_in[2];
    const float* wqkv  = (const float*)d_in[3];
    const float* wout  = (const float*)d_in[4];
    float* out = (float*)d_out;

    float* xn_ptr; cudaGetSymbolAddress((void**)&xn_ptr, g_xn);
    float* ao_ptr; cudaGetSymbolAddress((void**)&ao_ptr, g_ao);

    cudaFuncSetAttribute(attn_kernel,
                         cudaFuncAttributeMaxDynamicSharedMemorySize, ATTN_SMEM);

    // 1. LayerNorm
    ln_kernel<<<ROWS, 256>>>(x, gamma, beta);

    // 2. QKV projection with head-major scatter
    gemm128<3072, 0><<<dim3(3072/128, ROWS/128), 256>>>(xn_ptr, wqkv, nullptr);

    // 3. attention (flash, diagonal-masked)
    attn_kernel<<<dim3(SEQ/64, BATCH*HEADS), 256, ATTN_SMEM>>>();

    // 4. output projection
    gemm128<1024, 1><<<dim3(1024/128, ROWS/128), 256>>>(ao_ptr, wout, out);
}

// round 2
// speedup vs baseline: 4.2208x; 4.2208x over previous
#include <cuda_runtime.h>
#include <math.h>
#include <float.h>

#define DIM     1024
#define HEADS   16
#define DHEAD   64
#define INNER   1024
#define SEQ     2048
#define BATCH   2
#define ROWS    (BATCH * SEQ)        // 4096
#define ATTN_SCALE 0.125f
#define LN_EPS  1e-5f

// ---------------- scratch (__device__ globals: no runtime allocation) -------
__device__ float g_xn[(size_t)ROWS * DIM];
__device__ float g_q [(size_t)BATCH * HEADS * SEQ * DHEAD];
__device__ float g_k [(size_t)BATCH * HEADS * SEQ * DHEAD];
__device__ float g_v [(size_t)BATCH * HEADS * SEQ * DHEAD];
__device__ float g_ao[(size_t)ROWS * INNER];

// ---------------- helpers ----------------------------------------------------
__device__ __forceinline__ unsigned f2tf(float x) {
    unsigned u;
    asm("cvt.rna.tf32.f32 %0, %1;" : "=r"(u) : "f"(x));
    return u;
}
__device__ __forceinline__ uint4 f2tf4(float4 v) {
    uint4 r;
    r.x = f2tf(v.x); r.y = f2tf(v.y); r.z = f2tf(v.z); r.w = f2tf(v.w);
    return r;
}
__device__ __forceinline__ void mma_tf32(float* c,
    unsigned a0, unsigned a1, unsigned a2, unsigned a3,
    unsigned b0, unsigned b1)
{
    asm volatile(
      "mma.sync.aligned.m16n8k8.row.col.f32.tf32.tf32.f32 "
      "{%0,%1,%2,%3},{%4,%5,%6,%7},{%8,%9},{%0,%1,%2,%3};\n"
      : "+f"(c[0]), "+f"(c[1]), "+f"(c[2]), "+f"(c[3])
      : "r"(a0), "r"(a1), "r"(a2), "r"(a3), "r"(b0), "r"(b1));
}

// ---------------- LayerNorm: one block (256 thr) per row ---------------------
__global__ __launch_bounds__(256) void ln_kernel(
    const float* __restrict__ x,
    const float* __restrict__ gamma,
    const float* __restrict__ beta)
{
    int row = blockIdx.x;
    int t   = threadIdx.x;
    const float4* xr = (const float4*)(x + (size_t)row * DIM);
    float4 v = xr[t];

    __shared__ float red[32];
    float s = v.x + v.y + v.z + v.w;
    #pragma unroll
    for (int o = 16; o > 0; o >>= 1) s += __shfl_xor_sync(0xffffffffu, s, o);
    if ((t & 31) == 0) red[t >> 5] = s;
    __syncthreads();
    if (t < 32) {
        float z = (t < 8) ? red[t] : 0.f;
        #pragma unroll
        for (int o = 4; o > 0; o >>= 1) z += __shfl_xor_sync(0xffffffffu, z, o);
        if (t == 0) red[0] = z * (1.0f / DIM);
    }
    __syncthreads();
    float mu = red[0];
    __syncthreads();

    float4 d4 = make_float4(v.x - mu, v.y - mu, v.z - mu, v.w - mu);
    float s2 = d4.x*d4.x + d4.y*d4.y + d4.z*d4.z + d4.w*d4.w;
    #pragma unroll
    for (int o = 16; o > 0; o >>= 1) s2 += __shfl_xor_sync(0xffffffffu, s2, o);
    if ((t & 31) == 0) red[t >> 5] = s2;
    __syncthreads();
    if (t < 32) {
        float z = (t < 8) ? red[t] : 0.f;
        #pragma unroll
        for (int o = 4; o > 0; o >>= 1) z += __shfl_xor_sync(0xffffffffu, z, o);
        if (t == 0) red[0] = z * (1.0f / DIM);
    }
    __syncthreads();
    float rinv = rsqrtf(red[0] + LN_EPS);

    float4 g = ((const float4*)gamma)[t];
    float4 bt = ((const float4*)beta)[t];
    float4 o4;
    o4.x = d4.x * rinv * g.x + bt.x;
    o4.y = d4.y * rinv * g.y + bt.y;
    o4.z = d4.z * rinv * g.z + bt.z;
    o4.w = d4.w * rinv * g.w + bt.w;
    ((float4*)(g_xn + (size_t)row * DIM))[t] = o4;
}

// ---------------- TF32 GEMM: 128x128 tile, 256 threads, 8 warps --------------
// warp tile 64x32 (mt 4 x nt 4 of m16n8). K-step 32.
// MODE 0: C = g_xn @ w_qkv, head-major scatter into g_q/g_k/g_v
// MODE 1: C = g_ao @ w_out -> out
#define ASTR 40
#define BSTR 136
template<int NCOLS, int MODE>
__global__ __launch_bounds__(256) void gemm_tf32(
    const float* __restrict__ A,
    const float* __restrict__ Bw,
    float* __restrict__ C)
{
    __shared__ unsigned As[128 * ASTR];
    __shared__ unsigned Bs[32 * BSTR];

    int tid  = threadIdx.x;
    int wid  = tid >> 5, lane = tid & 31;
    int g    = lane >> 2, t = lane & 3;
    int wm   = wid & 1, wn = wid >> 1;        // warps: 2 along M, 4 along N
    int m0   = blockIdx.y * 128;
    int n0   = blockIdx.x * 128;

    float acc[4][4][4];
    #pragma unroll
    for (int i = 0; i < 4; i++)
        #pragma unroll
        for (int j = 0; j < 4; j++)
            #pragma unroll
            for (int q = 0; q < 4; q++) acc[i][j][q] = 0.f;

    for (int k0 = 0; k0 < 1024; k0 += 32) {
        // A tile 128x32: 1024 float4 / 256 thr = 4 each
        #pragma unroll
        for (int i = 0; i < 4; i++) {
            int idx = tid + i * 256;
            int r = idx >> 3, c4 = idx & 7;
            float4 v = *(const float4*)(A + (size_t)(m0 + r) * 1024 + k0 + c4 * 4);
            *(uint4*)&As[r * ASTR + c4 * 4] = f2tf4(v);
        }
        // B tile 32x128
        #pragma unroll
        for (int i = 0; i < 4; i++) {
            int idx = tid + i * 256;
            int r = idx >> 5, c4 = idx & 31;
            float4 v = *(const float4*)(Bw + (size_t)(k0 + r) * NCOLS + n0 + c4 * 4);
            *(uint4*)&Bs[r * BSTR + c4 * 4] = f2tf4(v);
        }
        __syncthreads();

        #pragma unroll
        for (int kk = 0; kk < 4; kk++) {
            int kb = kk * 8;
            unsigned a[4][4], b[4][2];
            #pragma unroll
            for (int mt = 0; mt < 4; mt++) {
                int mr = wm * 64 + mt * 16;
                a[mt][0] = As[(mr + g    ) * ASTR + kb + t    ];
                a[mt][1] = As[(mr + g + 8) * ASTR + kb + t    ];
                a[mt][2] = As[(mr + g    ) * ASTR + kb + t + 4];
                a[mt][3] = As[(mr + g + 8) * ASTR + kb + t + 4];
            }
            #pragma unroll
            for (int nt = 0; nt < 4; nt++) {
                int nc = wn * 32 + nt * 8 + g;
                b[nt][0] = Bs[(kb + t    ) * BSTR + nc];
                b[nt][1] = Bs[(kb + t + 4) * BSTR + nc];
            }
            #pragma unroll
            for (int mt = 0; mt < 4; mt++)
                #pragma unroll
                for (int nt = 0; nt < 4; nt++)
                    mma_tf32(acc[mt][nt], a[mt][0], a[mt][1], a[mt][2], a[mt][3],
                             b[nt][0], b[nt][1]);
        }
        __syncthreads();
    }

    // epilogue
    #pragma unroll
    for (int mt = 0; mt < 4; mt++) {
        #pragma unroll
        for (int half = 0; half < 2; half++) {
            int r = m0 + wm * 64 + mt * 16 + g + half * 8;
            #pragma unroll
            for (int nt = 0; nt < 4; nt++) {
                int c = n0 + wn * 32 + nt * 8 + 2 * t;
                float v0 = acc[mt][nt][half * 2 + 0];
                float v1 = acc[mt][nt][half * 2 + 1];
                if (MODE == 0) {
                    int which = c >> 10;
                    int cc = c & 1023;
                    int h  = cc >> 6;
                    int dd = cc & 63;
                    int b_ = r >> 11;
                    int n  = r & 2047;
                    float* dst = (which == 0) ? g_q : (which == 1) ? g_k : g_v;
                    *(float2*)&dst[(((size_t)b_ * HEADS + h) * SEQ + n) * DHEAD + dd]
                        = make_float2(v0, v1);
                } else {
                    *(float2*)&C[(size_t)r * NCOLS + c] = make_float2(v0, v1);
                }
            }
        }
    }
}

// ---------------- TF32 flash attention ---------------------------------------
// grid (SEQ/64, BATCH*HEADS), 128 threads (4 warps), each warp = 16 q-rows.
#define QSTR 68
#define KSTR 68
#define VSTR 72
#define PSTR 68
#define ATTN_SMEM ((64*QSTR + 64*KSTR + 64*VSTR + 4*16*PSTR) * (int)sizeof(float))

__global__ __launch_bounds__(128) void attn_tf32()
{
    int qt = blockIdx.x;
    int bh = blockIdx.y;
    const float* Qg = g_q + (size_t)bh * SEQ * DHEAD + (size_t)qt * 64 * DHEAD;
    const float* Kg = g_k + (size_t)bh * SEQ * DHEAD;
    const float* Vg = g_v + (size_t)bh * SEQ * DHEAD;

    extern __shared__ unsigned sm[];
    unsigned* Qs = sm;
    unsigned* Ks = Qs + 64 * QSTR;
    unsigned* Vs = Ks + 64 * KSTR;
    unsigned* Ps = Vs + 64 * VSTR;

    int tid  = threadIdx.x;
    int wid  = tid >> 5, lane = tid & 31;
    int g    = lane >> 2, t = lane & 3;
    int mb   = wid * 16;
    unsigned* Psw = Ps + wid * 16 * PSTR;

    // load+convert Q (64x64)
    #pragma unroll
    for (int i = 0; i < 8; i++) {
        int idx = tid + i * 128;
        int r = idx >> 4, c4 = idx & 15;
        float4 v = *(const float4*)(Qg + (size_t)r * DHEAD + c4 * 4);
        *(uint4*)&Qs[r * QSTR + c4 * 4] = f2tf4(v);
    }

    float o[8][4];
    #pragma unroll
    for (int nt = 0; nt < 8; nt++)
        #pragma unroll
        for (int q = 0; q < 4; q++) o[nt][q] = 0.f;
    float m_run0 = -INFINITY, m_run1 = -INFINITY;
    float l_run0 = 0.f, l_run1 = 0.f;

    int gi0 = qt * 64 + mb + g;
    int gi1 = gi0 + 8;

    for (int kt = 0; kt < SEQ / 64; kt++) {
        // load+convert K,V tiles
        #pragma unroll
        for (int i = 0; i < 8; i++) {
            int idx = tid + i * 128;
            int r = idx >> 4, c4 = idx & 15;
            float4 kv = *(const float4*)(Kg + (size_t)(kt * 64 + r) * DHEAD + c4 * 4);
            *(uint4*)&Ks[r * KSTR + c4 * 4] = f2tf4(kv);
            float4 vv = *(const float4*)(Vg + (size_t)(kt * 64 + r) * DHEAD + c4 * 4);
            *(uint4*)&Vs[r * VSTR + c4 * 4] = f2tf4(vv);
        }
        __syncthreads();

        // S = Q K^T
        float s[8][4];
        #pragma unroll
        for (int nt = 0; nt < 8; nt++)
            #pragma unroll
            for (int q = 0; q < 4; q++) s[nt][q] = 0.f;

        #pragma unroll
        for (int kk = 0; kk < 8; kk++) {
            int kb = kk * 8;
            unsigned a0 = Qs[(mb + g    ) * QSTR + kb + t    ];
            unsigned a1 = Qs[(mb + g + 8) * QSTR + kb + t    ];
            unsigned a2 = Qs[(mb + g    ) * QSTR + kb + t + 4];
            unsigned a3 = Qs[(mb + g + 8) * QSTR + kb + t + 4];
            #pragma unroll
            for (int nt = 0; nt < 8; nt++) {
                int n = nt * 8 + g;
                unsigned b0 = Ks[n * KSTR + kb + t    ];
                unsigned b1 = Ks[n * KSTR + kb + t + 4];
                mma_tf32(s[nt], a0, a1, a2, a3, b0, b1);
            }
        }

        // scale + diagonal mask
        #pragma unroll
        for (int nt = 0; nt < 8; nt++) {
            int gj = kt * 64 + nt * 8 + 2 * t;
            s[nt][0] *= ATTN_SCALE; s[nt][1] *= ATTN_SCALE;
            s[nt][2] *= ATTN_SCALE; s[nt][3] *= ATTN_SCALE;
            if (gi0 == gj    ) s[nt][0] = -1e30f;
            if (gi0 == gj + 1) s[nt][1] = -1e30f;
            if (gi1 == gj    ) s[nt][2] = -1e30f;
            if (gi1 == gj + 1) s[nt][3] = -1e30f;
        }

        // row max (across fragments + 4-lane groups)
        float mx0 = -INFINITY, mx1 = -INFINITY;
        #pragma unroll
        for (int nt = 0; nt < 8; nt++) {
            mx0 = fmaxf(mx0, fmaxf(s[nt][0], s[nt][1]));
            mx1 = fmaxf(mx1, fmaxf(s[nt][2], s[nt][3]));
        }
        #pragma unroll
        for (int off = 1; off <= 2; off <<= 1) {
            mx0 = fmaxf(mx0, __shfl_xor_sync(0xffffffffu, mx0, off));
            mx1 = fmaxf(mx1, __shfl_xor_sync(0xffffffffu, mx1, off));
        }
        float mn0 = fmaxf(m_run0, mx0);
        float mn1 = fmaxf(m_run1, mx1);
        float al0 = __expf(m_run0 - mn0);
        float al1 = __expf(m_run1 - mn1);
        m_run0 = mn0; m_run1 = mn1;
        l_run0 *= al0; l_run1 *= al1;
        #pragma unroll
        for (int nt = 0; nt < 8; nt++) {
            o[nt][0] *= al0; o[nt][1] *= al0;
            o[nt][2] *= al1; o[nt][3] *= al1;
        }

        // P = exp(S - m), store tf32 into per-warp smem
        #pragma unroll
        for (int nt = 0; nt < 8; nt++) {
            float p0 = __expf(s[nt][0] - mn0);
            float p1 = __expf(s[nt][1] - mn0);
            float p2 = __expf(s[nt][2] - mn1);
            float p3 = __expf(s[nt][3] - mn1);
            l_run0 += p0 + p1;
            l_run1 += p2 + p3;
            uint2 lo = make_uint2(f2tf(p0), f2tf(p1));
            uint2 hi = make_uint2(f2tf(p2), f2tf(p3));
            *(uint2*)&Psw[(g    ) * PSTR + nt * 8 + 2 * t] = lo;
            *(uint2*)&Psw[(g + 8) * PSTR + nt * 8 + 2 * t] = hi;
        }
        __syncwarp();

        // O += P @ V
        #pragma unroll
        for (int kk = 0; kk < 8; kk++) {
            int kb = kk * 8;
            unsigned a0 = Psw[(g    ) * PSTR + kb + t    ];
            unsigned a1 = Psw[(g + 8) * PSTR + kb + t    ];
            unsigned a2 = Psw[(g    ) * PSTR + kb + t + 4];
            unsigned a3 = Psw[(g + 8) * PSTR + kb + t + 4];
            #pragma unroll
            for (int nt = 0; nt < 8; nt++) {
                unsigned b0 = Vs[(kb + t    ) * VSTR + nt * 8 + g];
                unsigned b1 = Vs[(kb + t + 4) * VSTR + nt * 8 + g];
                mma_tf32(o[nt], a0, a1, a2, a3, b0, b1);
            }
        }
        __syncthreads();
    }

    // final row-sum reduce across the 4 lanes of each row group
    #pragma unroll
    for (int off = 1; off <= 2; off <<= 1) {
        l_run0 += __shfl_xor_sync(0xffffffffu, l_run0, off);
        l_run1 += __shfl_xor_sync(0xffffffffu, l_run1, off);
    }
    float inv0 = 1.0f / l_run0;
    float inv1 = 1.0f / l_run1;

    int b_ = bh / HEADS;
    int h  = bh % HEADS;
    int n0r = qt * 64 + mb + g;
    #pragma unroll
    for (int nt = 0; nt < 8; nt++) {
        int c = h * DHEAD + nt * 8 + 2 * t;
        *(float2*)&g_ao[((size_t)b_ * SEQ + n0r    ) * INNER + c]
            = make_float2(o[nt][0] * inv0, o[nt][1] * inv0);
        *(float2*)&g_ao[((size_t)b_ * SEQ + n0r + 8) * INNER + c]
            = make_float2(o[nt][2] * inv1, o[nt][3] * inv1);
    }
}

// ---------------- launcher ---------------------------------------------------
extern "C" void kernel_launch(void* const* d_in, const int* in_sizes, int n_in,
                              void* d_out, int out_size)
{
    const float* x     = (const float*)d_in[0];
    const float* gamma = (const float*)d_in[1];
    const float* beta  = (const float*)d_in[2];
    const float* wqkv  = (const float*)d_in[3];
    const float* wout  = (const float*)d_in[4];
    float* out = (float*)d_out;

    float* xn_ptr; cudaGetSymbolAddress((void**)&xn_ptr, g_xn);
    float* ao_ptr; cudaGetSymbolAddress((void**)&ao_ptr, g_ao);

    cudaFuncSetAttribute(attn_tf32,
                         cudaFuncAttributeMaxDynamicSharedMemorySize, ATTN_SMEM);

    ln_kernel<<<ROWS, 256>>>(x, gamma, beta);
    gemm_tf32<3072, 0><<<dim3(3072/128, ROWS/128), 256>>>(xn_ptr, wqkv, nullptr);
    attn_tf32<<<dim3(SEQ/64, BATCH*HEADS), 128, ATTN_SMEM>>>();
    gemm_tf32<1024, 1><<<dim3(1024/128, ROWS/128), 256>>>(ao_ptr, wout, out);
}

// round 4
// speedup vs baseline: 4.8749x; 1.1550x over previous
#include <cuda_runtime.h>
#include <math.h>
#include <float.h>

#define DIM     1024
#define HEADS   16
#define DHEAD   64
#define INNER   1024
#define SEQ     2048
#define BATCH   2
#define ROWS    (BATCH * SEQ)
#define ATTN_SCALE 0.125f
#define LN_EPS  1e-5f

// ---------------- scratch ----------------------------------------------------
__device__ float g_xn[(size_t)ROWS * DIM];
__device__ float g_q [(size_t)BATCH * HEADS * SEQ * DHEAD];
__device__ float g_k [(size_t)BATCH * HEADS * SEQ * DHEAD];
__device__ float g_v [(size_t)BATCH * HEADS * SEQ * DHEAD];
__device__ float g_ao[(size_t)ROWS * INNER];
__device__ float g_wqkv_tf[(size_t)DIM * 3 * INNER];
__device__ float g_wout_tf[(size_t)INNER * DIM];

// ---------------- helpers ----------------------------------------------------
__device__ __forceinline__ unsigned f2tf(float x) {
    unsigned u;
    asm("cvt.rna.tf32.f32 %0, %1;" : "=r"(u) : "f"(x));
    return u;
}
__device__ __forceinline__ uint4 f2tf4(float4 v) {
    uint4 r;
    r.x = f2tf(v.x); r.y = f2tf(v.y); r.z = f2tf(v.z); r.w = f2tf(v.w);
    return r;
}
__device__ __forceinline__ void mma_tf32(float* c,
    unsigned a0, unsigned a1, unsigned a2, unsigned a3,
    unsigned b0, unsigned b1)
{
    asm volatile(
      "mma.sync.aligned.m16n8k8.row.col.f32.tf32.tf32.f32 "
      "{%0,%1,%2,%3},{%4,%5,%6,%7},{%8,%9},{%0,%1,%2,%3};\n"
      : "+f"(c[0]), "+f"(c[1]), "+f"(c[2]), "+f"(c[3])
      : "r"(a0), "r"(a1), "r"(a2), "r"(a3), "r"(b0), "r"(b1));
}
__device__ __forceinline__ void cp16(void* sm, const void* g) {
    unsigned s = (unsigned)__cvta_generic_to_shared(sm);
    asm volatile("cp.async.cg.shared.global [%0], [%1], 16;\n" :: "r"(s), "l"(g));
}
__device__ __forceinline__ void cp_commit() {
    asm volatile("cp.async.commit_group;\n");
}
template<int N> __device__ __forceinline__ void cp_wait() {
    asm volatile("cp.async.wait_group %0;\n" :: "n"(N));
}

// ---------------- weight tf32 pre-round --------------------------------------
__global__ __launch_bounds__(256) void cvt_kernel(
    const float* __restrict__ in, float* __restrict__ outp)
{
    int i = blockIdx.x * 256 + threadIdx.x;
    float4 v = ((const float4*)in)[i];
    ((uint4*)outp)[i] = f2tf4(v);
}

// ---------------- LayerNorm (stores tf32-rounded) ----------------------------
__global__ __launch_bounds__(256) void ln_kernel(
    const float* __restrict__ x,
    const float* __restrict__ gamma,
    const float* __restrict__ beta)
{
    int row = blockIdx.x;
    int t   = threadIdx.x;
    const float4* xr = (const float4*)(x + (size_t)row * DIM);
    float4 v = xr[t];

    __shared__ float red[32];
    float s = v.x + v.y + v.z + v.w;
    #pragma unroll
    for (int o = 16; o > 0; o >>= 1) s += __shfl_xor_sync(0xffffffffu, s, o);
    if ((t & 31) == 0) red[t >> 5] = s;
    __syncthreads();
    if (t < 32) {
        float z = (t < 8) ? red[t] : 0.f;
        #pragma unroll
        for (int o = 4; o > 0; o >>= 1) z += __shfl_xor_sync(0xffffffffu, z, o);
        if (t == 0) red[0] = z * (1.0f / DIM);
    }
    __syncthreads();
    float mu = red[0];
    __syncthreads();

    float4 d4 = make_float4(v.x - mu, v.y - mu, v.z - mu, v.w - mu);
    float s2 = d4.x*d4.x + d4.y*d4.y + d4.z*d4.z + d4.w*d4.w;
    #pragma unroll
    for (int o = 16; o > 0; o >>= 1) s2 += __shfl_xor_sync(0xffffffffu, s2, o);
    if ((t & 31) == 0) red[t >> 5] = s2;
    __syncthreads();
    if (t < 32) {
        float z = (t < 8) ? red[t] : 0.f;
        #pragma unroll
        for (int o = 4; o > 0; o >>= 1) z += __shfl_xor_sync(0xffffffffu, z, o);
        if (t == 0) red[0] = z * (1.0f / DIM);
    }
    __syncthreads();
    float rinv = rsqrtf(red[0] + LN_EPS);

    float4 g = ((const float4*)gamma)[t];
    float4 bt = ((const float4*)beta)[t];
    float4 o4;
    o4.x = d4.x * rinv * g.x + bt.x;
    o4.y = d4.y * rinv * g.y + bt.y;
    o4.z = d4.z * rinv * g.z + bt.z;
    o4.w = d4.w * rinv * g.w + bt.w;
    ((uint4*)(g_xn + (size_t)row * DIM))[t] = f2tf4(o4);
}

// ---------------- TF32 GEMM, cp.async 2-stage pipeline -----------------------
// 128x128 tile, 256 threads, 8 warps (2M x 4N), warp tile 64x32, BK=32.
#define ASTR 36
#define BSTR 136
#define GEMM_SMEM ((2 * 128 * ASTR + 2 * 32 * BSTR) * (int)sizeof(float))

template<int NCOLS, int MODE>
__global__ __launch_bounds__(256) void gemm_tf32(
    const float* __restrict__ A,
    const float* __restrict__ Bw,
    float* __restrict__ C)
{
    extern __shared__ float smem[];
    float* Asm = smem;                       // 2 stages of 128*ASTR
    float* Bsm = smem + 2 * 128 * ASTR;      // 2 stages of 32*BSTR

    int tid  = threadIdx.x;
    int wid  = tid >> 5, lane = tid & 31;
    int g    = lane >> 2, t = lane & 3;
    int wm   = wid & 1, wn = wid >> 1;
    int m0   = blockIdx.y * 128;
    int n0   = blockIdx.x * 128;

    float acc[4][4][4];
    #pragma unroll
    for (int i = 0; i < 4; i++)
        #pragma unroll
        for (int j = 0; j < 4; j++)
            #pragma unroll
            for (int q = 0; q < 4; q++) acc[i][j][q] = 0.f;

    // stage issue
    auto issue = [&](int k0, int st) {
        float* Ad = Asm + st * 128 * ASTR;
        #pragma unroll
        for (int i = 0; i < 4; i++) {
            int idx = tid + i * 256;
            int r = idx >> 3, c = idx & 7;
            cp16(Ad + r * ASTR + c * 4,
                 A + (size_t)(m0 + r) * 1024 + k0 + c * 4);
        }
        float* Bd = Bsm + st * 32 * BSTR;
        #pragma unroll
        for (int i = 0; i < 4; i++) {
            int idx = tid + i * 256;
            int r = idx >> 5, c = idx & 31;
            cp16(Bd + r * BSTR + c * 4,
                 Bw + (size_t)(k0 + r) * NCOLS + n0 + c * 4);
        }
    };

    issue(0, 0); cp_commit();

    for (int k0 = 0, it = 0; k0 < 1024; k0 += 32, it++) {
        int st = it & 1;
        bool more = (k0 + 32 < 1024);
        if (more) { issue(k0 + 32, st ^ 1); cp_commit(); }
        if (more) cp_wait<1>(); else cp_wait<0>();
        __syncthreads();

        const unsigned* As = (const unsigned*)(Asm + st * 128 * ASTR);
        const unsigned* Bs = (const unsigned*)(Bsm + st * 32 * BSTR);

        #pragma unroll
        for (int kk = 0; kk < 4; kk++) {
            int kb = kk * 8;
            unsigned a[4][4], b[4][2];
            #pragma unroll
            for (int mt = 0; mt < 4; mt++) {
                int mr = wm * 64 + mt * 16;
                a[mt][0] = As[(mr + g    ) * ASTR + kb + t    ];
                a[mt][1] = As[(mr + g + 8) * ASTR + kb + t    ];
                a[mt][2] = As[(mr + g    ) * ASTR + kb + t + 4];
                a[mt][3] = As[(mr + g + 8) * ASTR + kb + t + 4];
            }
            #pragma unroll
            for (int nt = 0; nt < 4; nt++) {
                int nc = wn * 32 + nt * 8 + g;
                b[nt][0] = Bs[(kb + t    ) * BSTR + nc];
                b[nt][1] = Bs[(kb + t + 4) * BSTR + nc];
            }
            #pragma unroll
            for (int mt = 0; mt < 4; mt++)
                #pragma unroll
                for (int nt = 0; nt < 4; nt++)
                    mma_tf32(acc[mt][nt], a[mt][0], a[mt][1], a[mt][2], a[mt][3],
                             b[nt][0], b[nt][1]);
        }
        __syncthreads();
    }

    #pragma unroll
    for (int mt = 0; mt < 4; mt++) {
        #pragma unroll
        for (int half = 0; half < 2; half++) {
            int r = m0 + wm * 64 + mt * 16 + g + half * 8;
            #pragma unroll
            for (int nt = 0; nt < 4; nt++) {
                int c = n0 + wn * 32 + nt * 8 + 2 * t;
                float v0 = acc[mt][nt][half * 2 + 0];
                float v1 = acc[mt][nt][half * 2 + 1];
                if (MODE == 0) {
                    // round to tf32 for downstream tensor consumers
                    v0 = __uint_as_float(f2tf(v0));
                    v1 = __uint_as_float(f2tf(v1));
                    int which = c >> 10;
                    int cc = c & 1023;
                    int h  = cc >> 6;
                    int dd = cc & 63;
                    int b_ = r >> 11;
                    int n  = r & 2047;
                    float* dst = (which == 0) ? g_q : (which == 1) ? g_k : g_v;
                    *(float2*)&dst[(((size_t)b_ * HEADS + h) * SEQ + n) * DHEAD + dd]
                        = make_float2(v0, v1);
                } else {
                    *(float2*)&C[(size_t)r * NCOLS + c] = make_float2(v0, v1);
                }
            }
        }
    }
}

// ---------------- TF32 flash attention, cp.async double-buffered K/V ---------
// grid (SEQ/64, BATCH*HEADS), 128 threads (4 warps), each warp = 16 q-rows.
#define QSTR 68
#define KSTR 68
#define VSTR 72
#define PSTR 68
#define ATTN_SMEM ((64*QSTR + 2*64*KSTR + 2*64*VSTR + 4*16*PSTR) * (int)sizeof(float))

__global__ __launch_bounds__(128) void attn_tf32()
{
    int qt = blockIdx.x;
    int bh = blockIdx.y;
    const float* Qg = g_q + (size_t)bh * SEQ * DHEAD + (size_t)qt * 64 * DHEAD;
    const float* Kg = g_k + (size_t)bh * SEQ * DHEAD;
    const float* Vg = g_v + (size_t)bh * SEQ * DHEAD;

    extern __shared__ float sm[];
    float* Qf = sm;                            // 64*QSTR
    float* Kf = Qf + 64 * QSTR;                // 2 stages 64*KSTR
    float* Vf = Kf + 2 * 64 * KSTR;            // 2 stages 64*VSTR
    float* Pf = Vf + 2 * 64 * VSTR;            // 4*16*PSTR

    int tid  = threadIdx.x;
    int wid  = tid >> 5, lane = tid & 31;
    int g    = lane >> 2, t = lane & 3;
    int mb   = wid * 16;
    unsigned* Qs  = (unsigned*)Qf;
    unsigned* Psw = (unsigned*)(Pf + wid * 16 * PSTR);

    auto issueKV = [&](int kt, int st) {
        float* Kd = Kf + st * 64 * KSTR;
        float* Vd = Vf + st * 64 * VSTR;
        #pragma unroll
        for (int i = 0; i < 8; i++) {
            int idx = tid + i * 128;
            int r = idx >> 4, c = idx & 15;
            cp16(Kd + r * KSTR + c * 4,
                 Kg + (size_t)(kt * 64 + r) * DHEAD + c * 4);
            cp16(Vd + r * VSTR + c * 4,
                 Vg + (size_t)(kt * 64 + r) * DHEAD + c * 4);
        }
    };

    // group 0: Q + KV stage 0
    #pragma unroll
    for (int i = 0; i < 8; i++) {
        int idx = tid + i * 128;
        int r = idx >> 4, c = idx & 15;
        cp16(Qf + r * QSTR + c * 4, Qg + (size_t)r * DHEAD + c * 4);
    }
    issueKV(0, 0); cp_commit();

    float o[8][4];
    #pragma unroll
    for (int nt = 0; nt < 8; nt++)
        #pragma unroll
        for (int q = 0; q < 4; q++) o[nt][q] = 0.f;
    float m_run0 = -INFINITY, m_run1 = -INFINITY;
    float l_run0 = 0.f, l_run1 = 0.f;

    int gi0 = qt * 64 + mb + g;
    int gi1 = gi0 + 8;

    for (int kt = 0; kt < SEQ / 64; kt++) {
        int st = kt & 1;
        bool more = (kt + 1 < SEQ / 64);
        if (more) { issueKV(kt + 1, st ^ 1); cp_commit(); }
        if (more) cp_wait<1>(); else cp_wait<0>();
        __syncthreads();

        const unsigned* Ks = (const unsigned*)(Kf + st * 64 * KSTR);
        const unsigned* Vs = (const unsigned*)(Vf + st * 64 * VSTR);

        // S = Q K^T
        float s[8][4];
        #pragma unroll
        for (int nt = 0; nt < 8; nt++)
            #pragma unroll
            for (int q = 0; q < 4; q++) s[nt][q] = 0.f;

        #pragma unroll
        for (int kk = 0; kk < 8; kk++) {
            int kb = kk * 8;
            unsigned a0 = Qs[(mb + g    ) * QSTR + kb + t    ];
            unsigned a1 = Qs[(mb + g + 8) * QSTR + kb + t    ];
            unsigned a2 = Qs[(mb + g    ) * QSTR + kb + t + 4];
            unsigned a3 = Qs[(mb + g + 8) * QSTR + kb + t + 4];
            #pragma unroll
            for (int nt = 0; nt < 8; nt++) {
                int n = nt * 8 + g;
                unsigned b0 = Ks[n * KSTR + kb + t    ];
                unsigned b1 = Ks[n * KSTR + kb + t + 4];
                mma_tf32(s[nt], a0, a1, a2, a3, b0, b1);
            }
        }

        // scale + diagonal mask
        #pragma unroll
        for (int nt = 0; nt < 8; nt++) {
            int gj = kt * 64 + nt * 8 + 2 * t;
            s[nt][0] *= ATTN_SCALE; s[nt][1] *= ATTN_SCALE;
            s[nt][2] *= ATTN_SCALE; s[nt][3] *= ATTN_SCALE;
            if (gi0 == gj    ) s[nt][0] = -1e30f;
            if (gi0 == gj + 1) s[nt][1] = -1e30f;
            if (gi1 == gj    ) s[nt][2] = -1e30f;
            if (gi1 == gj + 1) s[nt][3] = -1e30f;
        }

        // online softmax
        float mx0 = -INFINITY, mx1 = -INFINITY;
        #pragma unroll
        for (int nt = 0; nt < 8; nt++) {
            mx0 = fmaxf(mx0, fmaxf(s[nt][0], s[nt][1]));
            mx1 = fmaxf(mx1, fmaxf(s[nt][2], s[nt][3]));
        }
        #pragma unroll
        for (int off = 1; off <= 2; off <<= 1) {
            mx0 = fmaxf(mx0, __shfl_xor_sync(0xffffffffu, mx0, off));
            mx1 = fmaxf(mx1, __shfl_xor_sync(0xffffffffu, mx1, off));
        }
        float mn0 = fmaxf(m_run0, mx0);
        float mn1 = fmaxf(m_run1, mx1);
        float al0 = __expf(m_run0 - mn0);
        float al1 = __expf(m_run1 - mn1);
        m_run0 = mn0; m_run1 = mn1;
        l_run0 *= al0; l_run1 *= al1;
        #pragma unroll
        for (int nt = 0; nt < 8; nt++) {
            o[nt][0] *= al0; o[nt][1] *= al0;
            o[nt][2] *= al1; o[nt][3] *= al1;
        }

        // P = exp(S - m) -> per-warp smem (tf32)
        #pragma unroll
        for (int nt = 0; nt < 8; nt++) {
            float p0 = __expf(s[nt][0] - mn0);
            float p1 = __expf(s[nt][1] - mn0);
            float p2 = __expf(s[nt][2] - mn1);
            float p3 = __expf(s[nt][3] - mn1);
            l_run0 += p0 + p1;
            l_run1 += p2 + p3;
            *(uint2*)&Psw[(g    ) * PSTR + nt * 8 + 2 * t] = make_uint2(f2tf(p0), f2tf(p1));
            *(uint2*)&Psw[(g + 8) * PSTR + nt * 8 + 2 * t] = make_uint2(f2tf(p2), f2tf(p3));
        }
        __syncwarp();

        // O += P @ V
        #pragma unroll
        for (int kk = 0; kk < 8; kk++) {
            int kb = kk * 8;
            unsigned a0 = Psw[(g    ) * PSTR + kb + t    ];
            unsigned a1 = Psw[(g + 8) * PSTR + kb + t    ];
            unsigned a2 = Psw[(g    ) * PSTR + kb + t + 4];
            unsigned a3 = Psw[(g + 8) * PSTR + kb + t + 4];
            #pragma unroll
            for (int nt = 0; nt < 8; nt++) {
                unsigned b0 = Vs[(kb + t    ) * VSTR + nt * 8 + g];
                unsigned b1 = Vs[(kb + t + 4) * VSTR + nt * 8 + g];
                mma_tf32(o[nt], a0, a1, a2, a3, b0, b1);
            }
        }
        __syncthreads();
    }

    #pragma unroll
    for (int off = 1; off <= 2; off <<= 1) {
        l_run0 += __shfl_xor_sync(0xffffffffu, l_run0, off);
        l_run1 += __shfl_xor_sync(0xffffffffu, l_run1, off);
    }
    float inv0 = 1.0f / l_run0;
    float inv1 = 1.0f / l_run1;

    int b_ = bh / HEADS;
    int h  = bh % HEADS;
    int n0r = qt * 64 + mb + g;
    #pragma unroll
    for (int nt = 0; nt < 8; nt++) {
        int c = h * DHEAD + nt * 8 + 2 * t;
        float a0 = __uint_as_float(f2tf(o[nt][0] * inv0));
        float a1 = __uint_as_float(f2tf(o[nt][1] * inv0));
        float a2 = __uint_as_float(f2tf(o[nt][2] * inv1));
        float a3 = __uint_as_float(f2tf(o[nt][3] * inv1));
        *(float2*)&g_ao[((size_t)b_ * SEQ + n0r    ) * INNER + c] = make_float2(a0, a1);
        *(float2*)&g_ao[((size_t)b_ * SEQ + n0r + 8) * INNER + c] = make_float2(a2, a3);
    }
}

// ---------------- launcher ---------------------------------------------------
extern "C" void kernel_launch(void* const* d_in, const int* in_sizes, int n_in,
                              void* d_out, int out_size)
{
    const float* x     = (const float*)d_in[0];
    const float* gamma = (const float*)d_in[1];
    const float* beta  = (const float*)d_in[2];
    const float* wqkv  = (const float*)d_in[3];
    const float* wout  = (const float*)d_in[4];
    float* out = (float*)d_out;

    float* xn_ptr;  cudaGetSymbolAddress((void**)&xn_ptr, g_xn);
    float* ao_ptr;  cudaGetSymbolAddress((void**)&ao_ptr, g_ao);
    float* wqkv_tf; cudaGetSymbolAddress((void**)&wqkv_tf, g_wqkv_tf);
    float* wout_tf; cudaGetSymbolAddress((void**)&wout_tf, g_wout_tf);

    cudaFuncSetAttribute(gemm_tf32<3072, 0>,
                         cudaFuncAttributeMaxDynamicSharedMemorySize, GEMM_SMEM);
    cudaFuncSetAttribute(gemm_tf32<1024, 1>,
                         cudaFuncAttributeMaxDynamicSharedMemorySize, GEMM_SMEM);
    cudaFuncSetAttribute(attn_tf32,
                         cudaFuncAttributeMaxDynamicSharedMemorySize, ATTN_SMEM);

    // weight pre-round (overlaps with LN on the same stream queue)
    cvt_kernel<<<(DIM * 3 * INNER) / (256 * 4), 256>>>(wqkv, wqkv_tf);
    cvt_kernel<<<(INNER * DIM) / (256 * 4), 256>>>(wout, wout_tf);

    ln_kernel<<<ROWS, 256>>>(x, gamma, beta);
    gemm_tf32<3072, 0><<<dim3(3072/128, ROWS/128), 256, GEMM_SMEM>>>(xn_ptr, wqkv_tf, nullptr);
    attn_tf32<<<dim3(SEQ/64, BATCH*HEADS), 128, ATTN_SMEM>>>();
    gemm_tf32<1024, 1><<<dim3(1024/128, ROWS/128), 256, GEMM_SMEM>>>(ao_ptr, wout_tf, out);
}